// round 5
// baseline (speedup 1.0000x reference)
#include <cuda_runtime.h>

#define NUSER 100000
#define NITEM 50000
#define NN    150000
#define EE    2400000
#define F     64
#define Q     4096
#define NEG_SLOPE 0.2f

// ---------------- device scratch (no allocs allowed) ----------------
__device__ __align__(16) float g_x[2][NN * F];    // [0]=online, [1]=target
__device__ __align__(16) float g_hi[NN * 2 * F];  // interleaved h: per node 32 float4s:
                                                  // [e0(2p), e0(2p+1), e1(2p), e1(2p+1)] for p=0..31
__device__ __align__(8)  float2 g_as2[NN];        // (as_online, as_target)
__device__ __align__(8)  float2 g_ad2[NN];        // (ad_online, ad_target)
__device__ int g_rowptr[NN + 1];
__device__ int g_fill[NN];
__device__ int g_col[EE];

__device__ __forceinline__ float lrelu(float v) { return fmaxf(v, NEG_SLOPE * v); }

// ---------------- CSR build ----------------
__global__ void zero_counts_kernel() {
    int i = blockIdx.x * blockDim.x + threadIdx.x;
    if (i < NN) g_fill[i] = 0;
}

__global__ void hist_kernel(const int* __restrict__ ei) {
    int i = blockIdx.x * blockDim.x + threadIdx.x;
    if (i < EE) atomicAdd(&g_fill[ei[EE + i]], 1);
}

__global__ void scan_kernel() {
    __shared__ int sb[1024];
    int t = threadIdx.x;
    const int CH = 147;
    int start = t * CH;
    int end = min(start + CH, NN);
    int s = 0;
    for (int i = start; i < end; i++) s += g_fill[i];
    sb[t] = s;
    __syncthreads();
    for (int o = 1; o < 1024; o <<= 1) {
        int v = 0;
        if (t >= o) v = sb[t - o];
        __syncthreads();
        if (t >= o) sb[t] += v;
        __syncthreads();
    }
    int run = (t == 0) ? 0 : sb[t - 1];
    for (int i = start; i < end; i++) {
        int cnt = g_fill[i];
        g_rowptr[i] = run;
        g_fill[i]   = run;
        run += cnt;
    }
    if (t == 1023) g_rowptr[NN] = sb[1023];
}

__global__ void scatter_kernel(const int* __restrict__ ei) {
    int i = blockIdx.x * blockDim.x + threadIdx.x;
    if (i < EE) {
        int d = ei[EE + i];
        int pos = atomicAdd(&g_fill[d], 1);
        g_col[pos] = ei[i];
    }
}

// ---------------- both-encoder concat ----------------
__global__ void concat2_kernel(const float4* __restrict__ ueo, const float4* __restrict__ ieo,
                               const float4* __restrict__ uet, const float4* __restrict__ iet) {
    int i = blockIdx.x * blockDim.x + threadIdx.x;
    const int PER = NN * (F / 4);
    const int UQ  = NUSER * (F / 4);
    if (i >= 2 * PER) return;
    int enc = (i >= PER) ? 1 : 0;
    int j = i - enc * PER;
    float4 v;
    if (j < UQ) v = enc ? uet[j] : ueo[j];
    else        v = enc ? iet[j - UQ] : ieo[j - UQ];
    ((float4*)g_x[enc])[j] = v;
}

// ---------------- gemm (h = x @ W) with fused attention dots ----------------
// Writes h into the encoder-interleaved g_hi layout.
__global__ void __launch_bounds__(256) gemm_dots_kernel(
    const float* __restrict__ Wo, const float* __restrict__ Wt,
    const float* __restrict__ aso, const float* __restrict__ ado,
    const float* __restrict__ ast, const float* __restrict__ adt) {
    int enc = blockIdx.y;
    const float* W   = enc ? Wt  : Wo;
    const float* avs = enc ? ast : aso;
    const float* avd = enc ? adt : ado;
    const float* X   = g_x[enc];

    __shared__ float Xs[64 * 64];
    int tid = threadIdx.x;
    int r0  = blockIdx.x * 64;
    int c   = tid & 63;
    int rb  = (tid >> 6) * 16;

    float Wc[64];
#pragma unroll
    for (int k = 0; k < 64; k++) Wc[k] = W[k * 64 + c];

    const float4* X4  = (const float4*)(X + (size_t)r0 * F);
    float4*       Xs4 = (float4*)Xs;
#pragma unroll
    for (int i = 0; i < 4; i++) {
        int idx = tid + i * 256;
        int row = idx >> 4;
        float4 v = make_float4(0.f, 0.f, 0.f, 0.f);
        if (r0 + row < NN) v = X4[idx];
        Xs4[idx] = v;
    }
    __syncthreads();

    float acc[16];
#pragma unroll
    for (int i = 0; i < 16; i++) acc[i] = 0.f;

#pragma unroll
    for (int kq = 0; kq < 16; kq++) {
#pragma unroll
        for (int i = 0; i < 16; i++) {
            float4 x4 = Xs4[(rb + i) * 16 + kq];
            acc[i] = fmaf(x4.x, Wc[4 * kq + 0], acc[i]);
            acc[i] = fmaf(x4.y, Wc[4 * kq + 1], acc[i]);
            acc[i] = fmaf(x4.z, Wc[4 * kq + 2], acc[i]);
            acc[i] = fmaf(x4.w, Wc[4 * kq + 3], acc[i]);
        }
    }

    // interleaved store: element (r, c, enc) -> r*128 + (c>>1)*4 + enc*2 + (c&1)
    int ioff = ((c >> 1) << 2) + (enc << 1) + (c & 1);
#pragma unroll
    for (int i = 0; i < 16; i++) {
        int r = r0 + rb + i;
        if (r < NN) g_hi[(size_t)r * 128 + ioff] = acc[i];
    }

    // fused dots: reuse Xs as the H tile
    __syncthreads();
#pragma unroll
    for (int i = 0; i < 16; i++) Xs[(rb + i) * 64 + c] = acc[i];
    __syncthreads();

    int wid = tid >> 5, lane = tid & 31;
    float a0 = avs[lane], a1 = avs[32 + lane];
    float d0 = avd[lane], d1 = avd[32 + lane];
#pragma unroll
    for (int rr = 0; rr < 8; rr++) {
        int r = wid * 8 + rr;
        float h0 = Xs[r * 64 + lane];
        float h1 = Xs[r * 64 + 32 + lane];
        float s  = h0 * a0 + h1 * a1;
        float dd = h0 * d0 + h1 * d1;
#pragma unroll
        for (int o = 16; o; o >>= 1) {
            s  += __shfl_xor_sync(0xffffffffu, s,  o);
            dd += __shfl_xor_sync(0xffffffffu, dd, o);
        }
        int gr = r0 + r;
        if (lane == 0 && gr < NN) {
            ((float*)g_as2)[2 * gr + enc] = s;
            ((float*)g_ad2)[2 * gr + enc] = dd;
        }
    }
}

// ---------------- single-pass dual-encoder GAT aggregation ----------------
__global__ void __launch_bounds__(256) agg2_kernel(const float* __restrict__ bo,
                                                   const float* __restrict__ bt) {
    int d = (blockIdx.x * blockDim.x + threadIdx.x) >> 5;
    int lane = threadIdx.x & 31;
    if (d >= NN) return;

    const float4* hi4 = (const float4*)g_hi;

    int s0 = g_rowptr[d];
    int s1 = g_rowptr[d + 1];
    float2 adv = g_ad2[d];
    float2 asv = g_as2[d];
    float m0 = lrelu(asv.x + adv.x);     // running maxes; self weight starts at 1
    float m1 = lrelu(asv.y + adv.y);

    float4 hd = hi4[(size_t)d * 32 + lane];
    float acc0x = hd.x, acc0y = hd.y;    // self message, weight exp(e_self - m) = 1
    float acc1x = hd.z, acc1y = hd.w;
    float den0 = (lane == 0) ? 1.f : 0.f;
    float den1 = den0;

    for (int base = s0; base < s1; base += 32) {
        int k = base + lane;
        bool valid = k < s1;
        int s = valid ? g_col[k] : 0;
        float e0 = -1e30f, e1 = -1e30f;
        if (valid) {
            float2 a = g_as2[s];
            e0 = lrelu(a.x + adv.x);
            e1 = lrelu(a.y + adv.y);
        }
        // warp-wide chunk maxes
        float c0 = e0, c1 = e1;
#pragma unroll
        for (int o = 16; o; o >>= 1) {
            c0 = fmaxf(c0, __shfl_xor_sync(0xffffffffu, c0, o));
            c1 = fmaxf(c1, __shfl_xor_sync(0xffffffffu, c1, o));
        }
        if (c0 > m0) { float sc = __expf(m0 - c0); acc0x *= sc; acc0y *= sc; den0 *= sc; m0 = c0; }
        if (c1 > m1) { float sc = __expf(m1 - c1); acc1x *= sc; acc1y *= sc; den1 *= sc; m1 = c1; }

        float w0 = valid ? __expf(e0 - m0) : 0.f;
        float w1 = valid ? __expf(e1 - m1) : 0.f;
        den0 += w0;
        den1 += w1;

        int cnt = min(32, s1 - base);
        int j = 0;
        // unroll-by-8: batch shfls, batch independent LDG.128s, then FMAs (MLP ~8)
        for (; j + 8 <= cnt; j += 8) {
            int sj[8];
#pragma unroll
            for (int u = 0; u < 8; u++) sj[u] = __shfl_sync(0xffffffffu, s, j + u);
            float4 v[8];
#pragma unroll
            for (int u = 0; u < 8; u++) v[u] = hi4[(size_t)sj[u] * 32 + lane];
#pragma unroll
            for (int u = 0; u < 8; u++) {
                float w0j = __shfl_sync(0xffffffffu, w0, j + u);
                float w1j = __shfl_sync(0xffffffffu, w1, j + u);
                acc0x = fmaf(w0j, v[u].x, acc0x);
                acc0y = fmaf(w0j, v[u].y, acc0y);
                acc1x = fmaf(w1j, v[u].z, acc1x);
                acc1y = fmaf(w1j, v[u].w, acc1y);
            }
        }
        if (j < cnt) {
            int rem = cnt - j;             // 1..7, warp-uniform
            int sj[7];
            float4 v[7];
#pragma unroll
            for (int u = 0; u < 7; u++)
                if (u < rem) sj[u] = __shfl_sync(0xffffffffu, s, j + u);
#pragma unroll
            for (int u = 0; u < 7; u++)
                if (u < rem) v[u] = hi4[(size_t)sj[u] * 32 + lane];
#pragma unroll
            for (int u = 0; u < 7; u++) {
                if (u < rem) {
                    float w0j = __shfl_sync(0xffffffffu, w0, j + u);
                    float w1j = __shfl_sync(0xffffffffu, w1, j + u);
                    acc0x = fmaf(w0j, v[u].x, acc0x);
                    acc0y = fmaf(w0j, v[u].y, acc0y);
                    acc1x = fmaf(w1j, v[u].z, acc1x);
                    acc1y = fmaf(w1j, v[u].w, acc1y);
                }
            }
        }
    }
#pragma unroll
    for (int o = 16; o; o >>= 1) {
        den0 += __shfl_xor_sync(0xffffffffu, den0, o);
        den1 += __shfl_xor_sync(0xffffffffu, den1, o);
    }
    float inv0 = 1.f / den0;
    float inv1 = 1.f / den1;

    float2 o0, o1;
    o0.x = acc0x * inv0 + bo[2 * lane];
    o0.y = acc0y * inv0 + bo[2 * lane + 1];
    o1.x = acc1x * inv1 + bt[2 * lane];
    o1.y = acc1y * inv1 + bt[2 * lane + 1];
    ((float2*)g_x[0])[(size_t)d * 32 + lane] = o0;
    ((float2*)g_x[1])[(size_t)d * 32 + lane] = o1;
}

// ---------------- predictor + output assembly ----------------
__global__ void __launch_bounds__(256) final_kernel(const float* __restrict__ pW,
                                                    const float* __restrict__ pb,
                                                    const int* __restrict__ user,
                                                    const int* __restrict__ item,
                                                    float* __restrict__ out) {
    __shared__ float Ws[64 * 65];
    __shared__ float rows[4 * 64];
    int tid = threadIdx.x;
    bool isU = blockIdx.x < (Q / 4);
    int qb = (isU ? blockIdx.x : blockIdx.x - (Q / 4)) * 4;

    for (int i = tid; i < 4096; i += 256) Ws[(i >> 6) * 65 + (i & 63)] = pW[i];

    int qr = tid >> 6, c = tid & 63;
    int q = qb + qr;
    int node = isU ? user[q] : (NUSER + item[q]);
    rows[qr * 64 + c] = g_x[0][(size_t)node * F + c];
    __syncthreads();

    float acc = pb[c];
#pragma unroll
    for (int k = 0; k < 64; k++) acc = fmaf(rows[qr * 64 + k], Ws[c * 65 + k], acc);

    size_t base = isU ? 0 : (size_t)2 * Q * F;
    out[base + (size_t)q * F + c] = acc;                                  // predicted
    out[base + (size_t)Q * F + (size_t)q * F + c] = g_x[1][(size_t)node * F + c];  // target
}

// ---------------- host ----------------
extern "C" void kernel_launch(void* const* d_in, const int* in_sizes, int n_in,
                              void* d_out, int out_size) {
    const float *uembo, *iembo, *Wo, *aso, *ado, *bo;
    const float *uembt, *iembt, *Wt, *ast, *adt, *bt;
    const float *pW, *pb;
    const int *user, *item, *ei;

    if (in_sizes[0] == Q) {  // setup_inputs dict order
        user  = (const int*)d_in[0];
        item  = (const int*)d_in[1];
        ei    = (const int*)d_in[2];
        uembo = (const float*)d_in[3];  iembo = (const float*)d_in[4];
        Wo    = (const float*)d_in[5];
        aso   = (const float*)d_in[6];  ado   = (const float*)d_in[7];  bo = (const float*)d_in[8];
        uembt = (const float*)d_in[9];  iembt = (const float*)d_in[10];
        Wt    = (const float*)d_in[11];
        ast   = (const float*)d_in[12]; adt   = (const float*)d_in[13]; bt = (const float*)d_in[14];
        pW    = (const float*)d_in[15]; pb    = (const float*)d_in[16];
    } else {                 // reference signature order
        uembo = (const float*)d_in[0];  iembo = (const float*)d_in[1];
        Wo    = (const float*)d_in[2];
        aso   = (const float*)d_in[3];  ado   = (const float*)d_in[4];  bo = (const float*)d_in[5];
        uembt = (const float*)d_in[6];  iembt = (const float*)d_in[7];
        Wt    = (const float*)d_in[8];
        ast   = (const float*)d_in[9];  adt   = (const float*)d_in[10]; bt = (const float*)d_in[11];
        pW    = (const float*)d_in[12]; pb    = (const float*)d_in[13];
        user  = (const int*)d_in[14];
        item  = (const int*)d_in[15];
        ei    = (const int*)d_in[16];
    }
    float* out = (float*)d_out;

    zero_counts_kernel<<<(NN + 255) / 256, 256>>>();
    hist_kernel<<<EE / 256, 256>>>(ei);
    scan_kernel<<<1, 1024>>>();
    scatter_kernel<<<EE / 256, 256>>>(ei);

    concat2_kernel<<<(2 * NN * (F / 4) + 255) / 256, 256>>>(
        (const float4*)uembo, (const float4*)iembo,
        (const float4*)uembt, (const float4*)iembt);

    const int GEMM_BLOCKS = (NN + 63) / 64;  // 2344
    const int WARP_BLOCKS = NN / 8;          // 18750

    for (int l = 0; l < 3; l++) {
        dim3 gg(GEMM_BLOCKS, 2);
        gemm_dots_kernel<<<gg, 256>>>(Wo + (size_t)l * F * F, Wt + (size_t)l * F * F,
                                      aso + l * F, ado + l * F, ast + l * F, adt + l * F);
        agg2_kernel<<<WARP_BLOCKS, 256>>>(bo + l * F, bt + l * F);
    }

    final_kernel<<<2 * (Q / 4), 256>>>(pW, pb, user, item, out);
}

// round 6
// speedup vs baseline: 1.4212x; 1.4212x over previous
#include <cuda_runtime.h>

#define NUSER 100000
#define NITEM 50000
#define NN    150000
#define EE    2400000
#define F     64
#define Q     4096
#define NEG_SLOPE 0.2f

// ---------------- device scratch (no allocs allowed) ----------------
__device__ __align__(16) float g_x[2][NN * F];    // [0]=online, [1]=target
__device__ __align__(16) float g_hi[NN * 2 * F];  // interleaved h: per node 32 float4s:
                                                  // [e0(2p), e0(2p+1), e1(2p), e1(2p+1)] for p=0..31
__device__ __align__(8)  float2 g_as2[NN];        // (as_online, as_target)
__device__ __align__(8)  float2 g_ad2[NN];        // (ad_online, ad_target)
__device__ int g_rowptr[NN + 1];
__device__ int g_fill[NN];
__device__ int g_col[EE];

__device__ __forceinline__ float lrelu(float v) { return fmaxf(v, NEG_SLOPE * v); }

// ---------------- CSR build ----------------
__global__ void zero_counts_kernel() {
    int i = blockIdx.x * blockDim.x + threadIdx.x;
    if (i < NN) g_fill[i] = 0;
}

__global__ void hist_kernel(const int* __restrict__ ei) {
    int i = blockIdx.x * blockDim.x + threadIdx.x;
    if (i < EE) atomicAdd(&g_fill[ei[EE + i]], 1);
}

__global__ void scan_kernel() {
    __shared__ int sb[1024];
    int t = threadIdx.x;
    const int CH = 147;
    int start = t * CH;
    int end = min(start + CH, NN);
    int s = 0;
    for (int i = start; i < end; i++) s += g_fill[i];
    sb[t] = s;
    __syncthreads();
    for (int o = 1; o < 1024; o <<= 1) {
        int v = 0;
        if (t >= o) v = sb[t - o];
        __syncthreads();
        if (t >= o) sb[t] += v;
        __syncthreads();
    }
    int run = (t == 0) ? 0 : sb[t - 1];
    for (int i = start; i < end; i++) {
        int cnt = g_fill[i];
        g_rowptr[i] = run;
        g_fill[i]   = run;
        run += cnt;
    }
    if (t == 1023) g_rowptr[NN] = sb[1023];
}

__global__ void scatter_kernel(const int* __restrict__ ei) {
    int i = blockIdx.x * blockDim.x + threadIdx.x;
    if (i < EE) {
        int d = ei[EE + i];
        int pos = atomicAdd(&g_fill[d], 1);
        g_col[pos] = ei[i];
    }
}

// ---------------- both-encoder concat ----------------
__global__ void concat2_kernel(const float4* __restrict__ ueo, const float4* __restrict__ ieo,
                               const float4* __restrict__ uet, const float4* __restrict__ iet) {
    int i = blockIdx.x * blockDim.x + threadIdx.x;
    const int PER = NN * (F / 4);
    const int UQ  = NUSER * (F / 4);
    if (i >= 2 * PER) return;
    int enc = (i >= PER) ? 1 : 0;
    int j = i - enc * PER;
    float4 v;
    if (j < UQ) v = enc ? uet[j] : ueo[j];
    else        v = enc ? iet[j - UQ] : ieo[j - UQ];
    ((float4*)g_x[enc])[j] = v;
}

// ---------------- gemm (h = x @ W) with fused attention dots ----------------
// Writes h into the encoder-interleaved g_hi layout.
__global__ void __launch_bounds__(256) gemm_dots_kernel(
    const float* __restrict__ Wo, const float* __restrict__ Wt,
    const float* __restrict__ aso, const float* __restrict__ ado,
    const float* __restrict__ ast, const float* __restrict__ adt) {
    int enc = blockIdx.y;
    const float* W   = enc ? Wt  : Wo;
    const float* avs = enc ? ast : aso;
    const float* avd = enc ? adt : ado;
    const float* X   = g_x[enc];

    __shared__ float Xs[64 * 64];
    int tid = threadIdx.x;
    int r0  = blockIdx.x * 64;
    int c   = tid & 63;
    int rb  = (tid >> 6) * 16;

    float Wc[64];
#pragma unroll
    for (int k = 0; k < 64; k++) Wc[k] = W[k * 64 + c];

    const float4* X4  = (const float4*)(g_x[enc] + (size_t)r0 * F);
    float4*       Xs4 = (float4*)Xs;
#pragma unroll
    for (int i = 0; i < 4; i++) {
        int idx = tid + i * 256;
        int row = idx >> 4;
        float4 v = make_float4(0.f, 0.f, 0.f, 0.f);
        if (r0 + row < NN) v = X4[idx];
        Xs4[idx] = v;
    }
    __syncthreads();
    (void)X;

    float acc[16];
#pragma unroll
    for (int i = 0; i < 16; i++) acc[i] = 0.f;

#pragma unroll
    for (int kq = 0; kq < 16; kq++) {
#pragma unroll
        for (int i = 0; i < 16; i++) {
            float4 x4 = Xs4[(rb + i) * 16 + kq];
            acc[i] = fmaf(x4.x, Wc[4 * kq + 0], acc[i]);
            acc[i] = fmaf(x4.y, Wc[4 * kq + 1], acc[i]);
            acc[i] = fmaf(x4.z, Wc[4 * kq + 2], acc[i]);
            acc[i] = fmaf(x4.w, Wc[4 * kq + 3], acc[i]);
        }
    }

    // interleaved store: element (r, c, enc) -> r*128 + (c>>1)*4 + enc*2 + (c&1)
    int ioff = ((c >> 1) << 2) + (enc << 1) + (c & 1);
#pragma unroll
    for (int i = 0; i < 16; i++) {
        int r = r0 + rb + i;
        if (r < NN) g_hi[(size_t)r * 128 + ioff] = acc[i];
    }

    // fused dots: reuse Xs as the H tile
    __syncthreads();
#pragma unroll
    for (int i = 0; i < 16; i++) Xs[(rb + i) * 64 + c] = acc[i];
    __syncthreads();

    int wid = tid >> 5, lane = tid & 31;
    float a0 = avs[lane], a1 = avs[32 + lane];
    float d0 = avd[lane], d1 = avd[32 + lane];
#pragma unroll
    for (int rr = 0; rr < 8; rr++) {
        int r = wid * 8 + rr;
        float h0 = Xs[r * 64 + lane];
        float h1 = Xs[r * 64 + 32 + lane];
        float s  = h0 * a0 + h1 * a1;
        float dd = h0 * d0 + h1 * d1;
#pragma unroll
        for (int o = 16; o; o >>= 1) {
            s  += __shfl_xor_sync(0xffffffffu, s,  o);
            dd += __shfl_xor_sync(0xffffffffu, dd, o);
        }
        int gr = r0 + r;
        if (lane == 0 && gr < NN) {
            ((float*)g_as2)[2 * gr + enc] = s;
            ((float*)g_ad2)[2 * gr + enc] = dd;
        }
    }
}

// ---------------- single-pass dual-encoder GAT aggregation ----------------
// Padded unroll-4 inner loop: invalid lanes carry s=0, w=0 so padded
// iterations are weight-0 no-ops; no remainder path, no divergence.
__global__ void __launch_bounds__(256) agg2_kernel(const float* __restrict__ bo,
                                                   const float* __restrict__ bt) {
    int d = (blockIdx.x * blockDim.x + threadIdx.x) >> 5;
    int lane = threadIdx.x & 31;
    if (d >= NN) return;

    const float4* hi4 = (const float4*)g_hi;

    int s0 = g_rowptr[d];
    int s1 = g_rowptr[d + 1];
    float2 adv = g_ad2[d];
    float2 asv = g_as2[d];
    float m0 = lrelu(asv.x + adv.x);     // running maxes; self weight starts at 1
    float m1 = lrelu(asv.y + adv.y);

    float4 hd = hi4[(size_t)d * 32 + lane];
    float acc0x = hd.x, acc0y = hd.y;    // self message, weight exp(e_self - m) = 1
    float acc1x = hd.z, acc1y = hd.w;
    float den0 = (lane == 0) ? 1.f : 0.f;
    float den1 = den0;

    for (int base = s0; base < s1; base += 32) {
        int k = base + lane;
        bool valid = k < s1;
        int s = valid ? g_col[k] : 0;
        float e0 = -1e30f, e1 = -1e30f;
        if (valid) {
            float2 a = g_as2[s];
            e0 = lrelu(a.x + adv.x);
            e1 = lrelu(a.y + adv.y);
        }
        // warp-wide chunk maxes
        float c0 = e0, c1 = e1;
#pragma unroll
        for (int o = 16; o; o >>= 1) {
            c0 = fmaxf(c0, __shfl_xor_sync(0xffffffffu, c0, o));
            c1 = fmaxf(c1, __shfl_xor_sync(0xffffffffu, c1, o));
        }
        if (c0 > m0) { float sc = __expf(m0 - c0); acc0x *= sc; acc0y *= sc; den0 *= sc; m0 = c0; }
        if (c1 > m1) { float sc = __expf(m1 - c1); acc1x *= sc; acc1y *= sc; den1 *= sc; m1 = c1; }

        float w0 = valid ? __expf(e0 - m0) : 0.f;
        float w1 = valid ? __expf(e1 - m1) : 0.f;
        den0 += w0;
        den1 += w1;

        int cnt = min(32, s1 - base);
        int padded = (cnt + 3) & ~3;     // warp-uniform; padded lanes have w=0, s=0
        for (int j = 0; j < padded; j += 4) {
            int sj0 = __shfl_sync(0xffffffffu, s, j + 0);
            int sj1 = __shfl_sync(0xffffffffu, s, j + 1);
            int sj2 = __shfl_sync(0xffffffffu, s, j + 2);
            int sj3 = __shfl_sync(0xffffffffu, s, j + 3);
            float4 v0 = hi4[(size_t)sj0 * 32 + lane];
            float4 v1 = hi4[(size_t)sj1 * 32 + lane];
            float4 v2 = hi4[(size_t)sj2 * 32 + lane];
            float4 v3 = hi4[(size_t)sj3 * 32 + lane];
            float a0w = __shfl_sync(0xffffffffu, w0, j + 0);
            float b0w = __shfl_sync(0xffffffffu, w1, j + 0);
            float a1w = __shfl_sync(0xffffffffu, w0, j + 1);
            float b1w = __shfl_sync(0xffffffffu, w1, j + 1);
            float a2w = __shfl_sync(0xffffffffu, w0, j + 2);
            float b2w = __shfl_sync(0xffffffffu, w1, j + 2);
            float a3w = __shfl_sync(0xffffffffu, w0, j + 3);
            float b3w = __shfl_sync(0xffffffffu, w1, j + 3);
            acc0x = fmaf(a0w, v0.x, acc0x);  acc0y = fmaf(a0w, v0.y, acc0y);
            acc1x = fmaf(b0w, v0.z, acc1x);  acc1y = fmaf(b0w, v0.w, acc1y);
            acc0x = fmaf(a1w, v1.x, acc0x);  acc0y = fmaf(a1w, v1.y, acc0y);
            acc1x = fmaf(b1w, v1.z, acc1x);  acc1y = fmaf(b1w, v1.w, acc1y);
            acc0x = fmaf(a2w, v2.x, acc0x);  acc0y = fmaf(a2w, v2.y, acc0y);
            acc1x = fmaf(b2w, v2.z, acc1x);  acc1y = fmaf(b2w, v2.w, acc1y);
            acc0x = fmaf(a3w, v3.x, acc0x);  acc0y = fmaf(a3w, v3.y, acc0y);
            acc1x = fmaf(b3w, v3.z, acc1x);  acc1y = fmaf(b3w, v3.w, acc1y);
        }
    }
#pragma unroll
    for (int o = 16; o; o >>= 1) {
        den0 += __shfl_xor_sync(0xffffffffu, den0, o);
        den1 += __shfl_xor_sync(0xffffffffu, den1, o);
    }
    float inv0 = 1.f / den0;
    float inv1 = 1.f / den1;

    float2 o0, o1;
    o0.x = acc0x * inv0 + bo[2 * lane];
    o0.y = acc0y * inv0 + bo[2 * lane + 1];
    o1.x = acc1x * inv1 + bt[2 * lane];
    o1.y = acc1y * inv1 + bt[2 * lane + 1];
    ((float2*)g_x[0])[(size_t)d * 32 + lane] = o0;
    ((float2*)g_x[1])[(size_t)d * 32 + lane] = o1;
}

// ---------------- predictor + output assembly ----------------
__global__ void __launch_bounds__(256) final_kernel(const float* __restrict__ pW,
                                                    const float* __restrict__ pb,
                                                    const int* __restrict__ user,
                                                    const int* __restrict__ item,
                                                    float* __restrict__ out) {
    __shared__ float Ws[64 * 65];
    __shared__ float rows[4 * 64];
    int tid = threadIdx.x;
    bool isU = blockIdx.x < (Q / 4);
    int qb = (isU ? blockIdx.x : blockIdx.x - (Q / 4)) * 4;

    for (int i = tid; i < 4096; i += 256) Ws[(i >> 6) * 65 + (i & 63)] = pW[i];

    int qr = tid >> 6, c = tid & 63;
    int q = qb + qr;
    int node = isU ? user[q] : (NUSER + item[q]);
    rows[qr * 64 + c] = g_x[0][(size_t)node * F + c];
    __syncthreads();

    float acc = pb[c];
#pragma unroll
    for (int k = 0; k < 64; k++) acc = fmaf(rows[qr * 64 + k], Ws[c * 65 + k], acc);

    size_t base = isU ? 0 : (size_t)2 * Q * F;
    out[base + (size_t)q * F + c] = acc;                                  // predicted
    out[base + (size_t)Q * F + (size_t)q * F + c] = g_x[1][(size_t)node * F + c];  // target
}

// ---------------- host ----------------
extern "C" void kernel_launch(void* const* d_in, const int* in_sizes, int n_in,
                              void* d_out, int out_size) {
    const float *uembo, *iembo, *Wo, *aso, *ado, *bo;
    const float *uembt, *iembt, *Wt, *ast, *adt, *bt;
    const float *pW, *pb;
    const int *user, *item, *ei;

    if (in_sizes[0] == Q) {  // setup_inputs dict order
        user  = (const int*)d_in[0];
        item  = (const int*)d_in[1];
        ei    = (const int*)d_in[2];
        uembo = (const float*)d_in[3];  iembo = (const float*)d_in[4];
        Wo    = (const float*)d_in[5];
        aso   = (const float*)d_in[6];  ado   = (const float*)d_in[7];  bo = (const float*)d_in[8];
        uembt = (const float*)d_in[9];  iembt = (const float*)d_in[10];
        Wt    = (const float*)d_in[11];
        ast   = (const float*)d_in[12]; adt   = (const float*)d_in[13]; bt = (const float*)d_in[14];
        pW    = (const float*)d_in[15]; pb    = (const float*)d_in[16];
    } else {                 // reference signature order
        uembo = (const float*)d_in[0];  iembo = (const float*)d_in[1];
        Wo    = (const float*)d_in[2];
        aso   = (const float*)d_in[3];  ado   = (const float*)d_in[4];  bo = (const float*)d_in[5];
        uembt = (const float*)d_in[6];  iembt = (const float*)d_in[7];
        Wt    = (const float*)d_in[8];
        ast   = (const float*)d_in[9];  adt   = (const float*)d_in[10]; bt = (const float*)d_in[11];
        pW    = (const float*)d_in[12]; pb    = (const float*)d_in[13];
        user  = (const int*)d_in[14];
        item  = (const int*)d_in[15];
        ei    = (const int*)d_in[16];
    }
    float* out = (float*)d_out;

    zero_counts_kernel<<<(NN + 255) / 256, 256>>>();
    hist_kernel<<<EE / 256, 256>>>(ei);
    scan_kernel<<<1, 1024>>>();
    scatter_kernel<<<EE / 256, 256>>>(ei);

    concat2_kernel<<<(2 * NN * (F / 4) + 255) / 256, 256>>>(
        (const float4*)uembo, (const float4*)iembo,
        (const float4*)uembt, (const float4*)iembt);

    const int GEMM_BLOCKS = (NN + 63) / 64;  // 2344
    const int WARP_BLOCKS = NN / 8;          // 18750

    for (int l = 0; l < 3; l++) {
        dim3 gg(GEMM_BLOCKS, 2);
        gemm_dots_kernel<<<gg, 256>>>(Wo + (size_t)l * F * F, Wt + (size_t)l * F * F,
                                      aso + l * F, ado + l * F, ast + l * F, adt + l * F);
        agg2_kernel<<<WARP_BLOCKS, 256>>>(bo + l * F, bt + l * F);
    }

    final_kernel<<<2 * (Q / 4), 256>>>(pW, pb, user, item, out);
}

// round 7
// speedup vs baseline: 1.6600x; 1.1680x over previous
#include <cuda_runtime.h>
#include <cuda_fp16.h>

#define NUSER 100000
#define NITEM 50000
#define NN    150000
#define EE    2400000
#define F     64
#define Q     4096
#define NEG_SLOPE 0.2f

// ---------------- device scratch (no allocs allowed) ----------------
__device__ __align__(16) float  g_x[2][NN * F];   // [0]=online, [1]=target (fp32)
__device__ __align__(16) __half g_hih[NN * 2 * F]; // fp16 interleaved h: per node 128 halves:
                                                   // idx = r*128 + (c>>1)*4 + enc*2 + (c&1)
__device__ __align__(8)  float2 g_as2[NN];        // (as_online, as_target) fp32
__device__ __align__(8)  float2 g_ad2[NN];        // (ad_online, ad_target) fp32
__device__ int g_rowptr[NN + 1];
__device__ int g_fill[NN];
__device__ int g_col[EE];

__device__ __forceinline__ float lrelu(float v) { return fmaxf(v, NEG_SLOPE * v); }

// ---------------- CSR build ----------------
__global__ void zero_counts_kernel() {
    int i = blockIdx.x * blockDim.x + threadIdx.x;
    if (i < NN) g_fill[i] = 0;
}

__global__ void hist_kernel(const int* __restrict__ ei) {
    int i = blockIdx.x * blockDim.x + threadIdx.x;
    if (i < EE) atomicAdd(&g_fill[ei[EE + i]], 1);
}

__global__ void scan_kernel() {
    __shared__ int sb[1024];
    int t = threadIdx.x;
    const int CH = 147;
    int start = t * CH;
    int end = min(start + CH, NN);
    int s = 0;
    for (int i = start; i < end; i++) s += g_fill[i];
    sb[t] = s;
    __syncthreads();
    for (int o = 1; o < 1024; o <<= 1) {
        int v = 0;
        if (t >= o) v = sb[t - o];
        __syncthreads();
        if (t >= o) sb[t] += v;
        __syncthreads();
    }
    int run = (t == 0) ? 0 : sb[t - 1];
    for (int i = start; i < end; i++) {
        int cnt = g_fill[i];
        g_rowptr[i] = run;
        g_fill[i]   = run;
        run += cnt;
    }
    if (t == 1023) g_rowptr[NN] = sb[1023];
}

__global__ void scatter_kernel(const int* __restrict__ ei) {
    int i = blockIdx.x * blockDim.x + threadIdx.x;
    if (i < EE) {
        int d = ei[EE + i];
        int pos = atomicAdd(&g_fill[d], 1);
        g_col[pos] = ei[i];
    }
}

// ---------------- both-encoder concat ----------------
__global__ void concat2_kernel(const float4* __restrict__ ueo, const float4* __restrict__ ieo,
                               const float4* __restrict__ uet, const float4* __restrict__ iet) {
    int i = blockIdx.x * blockDim.x + threadIdx.x;
    const int PER = NN * (F / 4);
    const int UQ  = NUSER * (F / 4);
    if (i >= 2 * PER) return;
    int enc = (i >= PER) ? 1 : 0;
    int j = i - enc * PER;
    float4 v;
    if (j < UQ) v = enc ? uet[j] : ueo[j];
    else        v = enc ? iet[j - UQ] : ieo[j - UQ];
    ((float4*)g_x[enc])[j] = v;
}

// ---------------- gemm (h = x @ W) with fused attention dots ----------------
// Writes h (fp16) into the encoder-interleaved g_hih layout; dots in fp32.
__global__ void __launch_bounds__(256) gemm_dots_kernel(
    const float* __restrict__ Wo, const float* __restrict__ Wt,
    const float* __restrict__ aso, const float* __restrict__ ado,
    const float* __restrict__ ast, const float* __restrict__ adt) {
    int enc = blockIdx.y;
    const float* W   = enc ? Wt  : Wo;
    const float* avs = enc ? ast : aso;
    const float* avd = enc ? adt : ado;

    __shared__ float Xs[64 * 64];
    int tid = threadIdx.x;
    int r0  = blockIdx.x * 64;
    int c   = tid & 63;
    int rb  = (tid >> 6) * 16;

    float Wc[64];
#pragma unroll
    for (int k = 0; k < 64; k++) Wc[k] = W[k * 64 + c];

    const float4* X4  = (const float4*)(g_x[enc] + (size_t)r0 * F);
    float4*       Xs4 = (float4*)Xs;
#pragma unroll
    for (int i = 0; i < 4; i++) {
        int idx = tid + i * 256;
        int row = idx >> 4;
        float4 v = make_float4(0.f, 0.f, 0.f, 0.f);
        if (r0 + row < NN) v = X4[idx];
        Xs4[idx] = v;
    }
    __syncthreads();

    float acc[16];
#pragma unroll
    for (int i = 0; i < 16; i++) acc[i] = 0.f;

#pragma unroll
    for (int kq = 0; kq < 16; kq++) {
#pragma unroll
        for (int i = 0; i < 16; i++) {
            float4 x4 = Xs4[(rb + i) * 16 + kq];
            acc[i] = fmaf(x4.x, Wc[4 * kq + 0], acc[i]);
            acc[i] = fmaf(x4.y, Wc[4 * kq + 1], acc[i]);
            acc[i] = fmaf(x4.z, Wc[4 * kq + 2], acc[i]);
            acc[i] = fmaf(x4.w, Wc[4 * kq + 3], acc[i]);
        }
    }

    // interleaved fp16 store: (r, c, enc) -> r*128 + (c>>1)*4 + enc*2 + (c&1)
    int ioff = ((c >> 1) << 2) + (enc << 1) + (c & 1);
#pragma unroll
    for (int i = 0; i < 16; i++) {
        int r = r0 + rb + i;
        if (r < NN) g_hih[(size_t)r * 128 + ioff] = __float2half(acc[i]);
    }

    // fused dots: reuse Xs as the H tile (fp32, unquantized)
    __syncthreads();
#pragma unroll
    for (int i = 0; i < 16; i++) Xs[(rb + i) * 64 + c] = acc[i];
    __syncthreads();

    int wid = tid >> 5, lane = tid & 31;
    float a0 = avs[lane], a1 = avs[32 + lane];
    float d0 = avd[lane], d1 = avd[32 + lane];
#pragma unroll
    for (int rr = 0; rr < 8; rr++) {
        int r = wid * 8 + rr;
        float h0 = Xs[r * 64 + lane];
        float h1 = Xs[r * 64 + 32 + lane];
        float s  = h0 * a0 + h1 * a1;
        float dd = h0 * d0 + h1 * d1;
#pragma unroll
        for (int o = 16; o; o >>= 1) {
            s  += __shfl_xor_sync(0xffffffffu, s,  o);
            dd += __shfl_xor_sync(0xffffffffu, dd, o);
        }
        int gr = r0 + r;
        if (lane == 0 && gr < NN) {
            ((float*)g_as2)[2 * gr + enc] = s;
            ((float*)g_ad2)[2 * gr + enc] = dd;
        }
    }
}

// ---------------- single-pass dual-encoder GAT aggregation (fp16 messages) ----
__global__ void __launch_bounds__(256) agg2_kernel(const float* __restrict__ bo,
                                                   const float* __restrict__ bt) {
    int d = (blockIdx.x * blockDim.x + threadIdx.x) >> 5;
    int lane = threadIdx.x & 31;
    if (d >= NN) return;

    const uint2* hi2 = (const uint2*)g_hih;   // 8 B per lane per node

    int s0 = g_rowptr[d];
    int s1 = g_rowptr[d + 1];
    float2 adv = g_ad2[d];
    float2 asv = g_as2[d];
    float m0 = lrelu(asv.x + adv.x);     // running maxes; self weight starts at 1
    float m1 = lrelu(asv.y + adv.y);

    uint2 hd = hi2[(size_t)d * 32 + lane];
    float2 f0 = __half22float2(*(__half2*)&hd.x);
    float2 f1 = __half22float2(*(__half2*)&hd.y);
    float acc0x = f0.x, acc0y = f0.y;    // self message, weight exp(e_self - m) = 1
    float acc1x = f1.x, acc1y = f1.y;
    float den0 = (lane == 0) ? 1.f : 0.f;
    float den1 = den0;

    for (int base = s0; base < s1; base += 32) {
        int k = base + lane;
        bool valid = k < s1;
        int s = valid ? g_col[k] : 0;
        float e0 = -1e30f, e1 = -1e30f;
        if (valid) {
            float2 a = g_as2[s];
            e0 = lrelu(a.x + adv.x);
            e1 = lrelu(a.y + adv.y);
        }
        // warp-wide chunk maxes
        float c0 = e0, c1 = e1;
#pragma unroll
        for (int o = 16; o; o >>= 1) {
            c0 = fmaxf(c0, __shfl_xor_sync(0xffffffffu, c0, o));
            c1 = fmaxf(c1, __shfl_xor_sync(0xffffffffu, c1, o));
        }
        if (c0 > m0) { float sc = __expf(m0 - c0); acc0x *= sc; acc0y *= sc; den0 *= sc; m0 = c0; }
        if (c1 > m1) { float sc = __expf(m1 - c1); acc1x *= sc; acc1y *= sc; den1 *= sc; m1 = c1; }

        float w0 = valid ? __expf(e0 - m0) : 0.f;
        float w1 = valid ? __expf(e1 - m1) : 0.f;
        den0 += w0;
        den1 += w1;

        int cnt = min(32, s1 - base);
        int padded = (cnt + 3) & ~3;     // padded lanes carry w=0, s=0 -> no-ops
        for (int j = 0; j < padded; j += 4) {
            int sj0 = __shfl_sync(0xffffffffu, s, j + 0);
            int sj1 = __shfl_sync(0xffffffffu, s, j + 1);
            int sj2 = __shfl_sync(0xffffffffu, s, j + 2);
            int sj3 = __shfl_sync(0xffffffffu, s, j + 3);
            uint2 v0 = hi2[(size_t)sj0 * 32 + lane];
            uint2 v1 = hi2[(size_t)sj1 * 32 + lane];
            uint2 v2 = hi2[(size_t)sj2 * 32 + lane];
            uint2 v3 = hi2[(size_t)sj3 * 32 + lane];
            float a0w = __shfl_sync(0xffffffffu, w0, j + 0);
            float b0w = __shfl_sync(0xffffffffu, w1, j + 0);
            float a1w = __shfl_sync(0xffffffffu, w0, j + 1);
            float b1w = __shfl_sync(0xffffffffu, w1, j + 1);
            float a2w = __shfl_sync(0xffffffffu, w0, j + 2);
            float b2w = __shfl_sync(0xffffffffu, w1, j + 2);
            float a3w = __shfl_sync(0xffffffffu, w0, j + 3);
            float b3w = __shfl_sync(0xffffffffu, w1, j + 3);
            float2 p, q;
            p = __half22float2(*(__half2*)&v0.x); q = __half22float2(*(__half2*)&v0.y);
            acc0x = fmaf(a0w, p.x, acc0x);  acc0y = fmaf(a0w, p.y, acc0y);
            acc1x = fmaf(b0w, q.x, acc1x);  acc1y = fmaf(b0w, q.y, acc1y);
            p = __half22float2(*(__half2*)&v1.x); q = __half22float2(*(__half2*)&v1.y);
            acc0x = fmaf(a1w, p.x, acc0x);  acc0y = fmaf(a1w, p.y, acc0y);
            acc1x = fmaf(b1w, q.x, acc1x);  acc1y = fmaf(b1w, q.y, acc1y);
            p = __half22float2(*(__half2*)&v2.x); q = __half22float2(*(__half2*)&v2.y);
            acc0x = fmaf(a2w, p.x, acc0x);  acc0y = fmaf(a2w, p.y, acc0y);
            acc1x = fmaf(b2w, q.x, acc1x);  acc1y = fmaf(b2w, q.y, acc1y);
            p = __half22float2(*(__half2*)&v3.x); q = __half22float2(*(__half2*)&v3.y);
            acc0x = fmaf(a3w, p.x, acc0x);  acc0y = fmaf(a3w, p.y, acc0y);
            acc1x = fmaf(b3w, q.x, acc1x);  acc1y = fmaf(b3w, q.y, acc1y);
        }
    }
#pragma unroll
    for (int o = 16; o; o >>= 1) {
        den0 += __shfl_xor_sync(0xffffffffu, den0, o);
        den1 += __shfl_xor_sync(0xffffffffu, den1, o);
    }
    float inv0 = 1.f / den0;
    float inv1 = 1.f / den1;

    float2 o0, o1;
    o0.x = acc0x * inv0 + bo[2 * lane];
    o0.y = acc0y * inv0 + bo[2 * lane + 1];
    o1.x = acc1x * inv1 + bt[2 * lane];
    o1.y = acc1y * inv1 + bt[2 * lane + 1];
    ((float2*)g_x[0])[(size_t)d * 32 + lane] = o0;
    ((float2*)g_x[1])[(size_t)d * 32 + lane] = o1;
}

// ---------------- predictor + output assembly ----------------
__global__ void __launch_bounds__(256) final_kernel(const float* __restrict__ pW,
                                                    const float* __restrict__ pb,
                                                    const int* __restrict__ user,
                                                    const int* __restrict__ item,
                                                    float* __restrict__ out) {
    __shared__ float Ws[64 * 65];
    __shared__ float rows[4 * 64];
    int tid = threadIdx.x;
    bool isU = blockIdx.x < (Q / 4);
    int qb = (isU ? blockIdx.x : blockIdx.x - (Q / 4)) * 4;

    for (int i = tid; i < 4096; i += 256) Ws[(i >> 6) * 65 + (i & 63)] = pW[i];

    int qr = tid >> 6, c = tid & 63;
    int q = qb + qr;
    int node = isU ? user[q] : (NUSER + item[q]);
    rows[qr * 64 + c] = g_x[0][(size_t)node * F + c];
    __syncthreads();

    float acc = pb[c];
#pragma unroll
    for (int k = 0; k < 64; k++) acc = fmaf(rows[qr * 64 + k], Ws[c * 65 + k], acc);

    size_t base = isU ? 0 : (size_t)2 * Q * F;
    out[base + (size_t)q * F + c] = acc;                                  // predicted
    out[base + (size_t)Q * F + (size_t)q * F + c] = g_x[1][(size_t)node * F + c];  // target
}

// ---------------- host ----------------
extern "C" void kernel_launch(void* const* d_in, const int* in_sizes, int n_in,
                              void* d_out, int out_size) {
    const float *uembo, *iembo, *Wo, *aso, *ado, *bo;
    const float *uembt, *iembt, *Wt, *ast, *adt, *bt;
    const float *pW, *pb;
    const int *user, *item, *ei;

    if (in_sizes[0] == Q) {  // setup_inputs dict order
        user  = (const int*)d_in[0];
        item  = (const int*)d_in[1];
        ei    = (const int*)d_in[2];
        uembo = (const float*)d_in[3];  iembo = (const float*)d_in[4];
        Wo    = (const float*)d_in[5];
        aso   = (const float*)d_in[6];  ado   = (const float*)d_in[7];  bo = (const float*)d_in[8];
        uembt = (const float*)d_in[9];  iembt = (const float*)d_in[10];
        Wt    = (const float*)d_in[11];
        ast   = (const float*)d_in[12]; adt   = (const float*)d_in[13]; bt = (const float*)d_in[14];
        pW    = (const float*)d_in[15]; pb    = (const float*)d_in[16];
    } else {                 // reference signature order
        uembo = (const float*)d_in[0];  iembo = (const float*)d_in[1];
        Wo    = (const float*)d_in[2];
        aso   = (const float*)d_in[3];  ado   = (const float*)d_in[4];  bo = (const float*)d_in[5];
        uembt = (const float*)d_in[6];  iembt = (const float*)d_in[7];
        Wt    = (const float*)d_in[8];
        ast   = (const float*)d_in[9];  adt   = (const float*)d_in[10]; bt = (const float*)d_in[11];
        pW    = (const float*)d_in[12]; pb    = (const float*)d_in[13];
        user  = (const int*)d_in[14];
        item  = (const int*)d_in[15];
        ei    = (const int*)d_in[16];
    }
    float* out = (float*)d_out;

    zero_counts_kernel<<<(NN + 255) / 256, 256>>>();
    hist_kernel<<<EE / 256, 256>>>(ei);
    scan_kernel<<<1, 1024>>>();
    scatter_kernel<<<EE / 256, 256>>>(ei);

    concat2_kernel<<<(2 * NN * (F / 4) + 255) / 256, 256>>>(
        (const float4*)uembo, (const float4*)iembo,
        (const float4*)uembt, (const float4*)iembt);

    const int GEMM_BLOCKS = (NN + 63) / 64;  // 2344
    const int WARP_BLOCKS = NN / 8;          // 18750

    for (int l = 0; l < 3; l++) {
        dim3 gg(GEMM_BLOCKS, 2);
        gemm_dots_kernel<<<gg, 256>>>(Wo + (size_t)l * F * F, Wt + (size_t)l * F * F,
                                      aso + l * F, ado + l * F, ast + l * F, adt + l * F);
        agg2_kernel<<<WARP_BLOCKS, 256>>>(bo + l * F, bt + l * F);
    }

    final_kernel<<<2 * (Q / 4), 256>>>(pW, pb, user, item, out);
}

// round 8
// speedup vs baseline: 1.7366x; 1.0462x over previous
#include <cuda_runtime.h>
#include <cuda_fp16.h>
#include <mma.h>
using namespace nvcuda;

#define NUSER 100000
#define NITEM 50000
#define NN    150000
#define EE    2400000
#define F     64
#define Q     4096
#define GR    128               // rows per gemm block
#define NEG_SLOPE 0.2f

// ---------------- device scratch (no allocs allowed) ----------------
__device__ __align__(16) float  g_x[2][NN * F];    // [0]=online, [1]=target (fp32)
__device__ __align__(16) __half g_hih[NN * 2 * F]; // fp16 interleaved h:
                                                   // idx = r*128 + (c>>1)*4 + enc*2 + (c&1)
__device__ __align__(8)  float2 g_as2[NN];         // (as_online, as_target) fp32
__device__ __align__(8)  float2 g_ad2[NN];         // (ad_online, ad_target) fp32
__device__ int g_rowptr[NN + 1];
__device__ int g_fill[NN];
__device__ int g_col[EE];

__device__ __forceinline__ float lrelu(float v) { return fmaxf(v, NEG_SLOPE * v); }

// ---------------- CSR build ----------------
__global__ void zero_counts_kernel() {
    int i = blockIdx.x * blockDim.x + threadIdx.x;
    if (i < NN) g_fill[i] = 0;
}

__global__ void hist_kernel(const int* __restrict__ ei) {
    int i = blockIdx.x * blockDim.x + threadIdx.x;
    if (i < EE) atomicAdd(&g_fill[ei[EE + i]], 1);
}

__global__ void scan_kernel() {
    __shared__ int sb[1024];
    int t = threadIdx.x;
    const int CH = 147;
    int start = t * CH;
    int end = min(start + CH, NN);
    int s = 0;
    for (int i = start; i < end; i++) s += g_fill[i];
    sb[t] = s;
    __syncthreads();
    for (int o = 1; o < 1024; o <<= 1) {
        int v = 0;
        if (t >= o) v = sb[t - o];
        __syncthreads();
        if (t >= o) sb[t] += v;
        __syncthreads();
    }
    int run = (t == 0) ? 0 : sb[t - 1];
    for (int i = start; i < end; i++) {
        int cnt = g_fill[i];
        g_rowptr[i] = run;
        g_fill[i]   = run;
        run += cnt;
    }
    if (t == 1023) g_rowptr[NN] = sb[1023];
}

__global__ void scatter_kernel(const int* __restrict__ ei) {
    int i = blockIdx.x * blockDim.x + threadIdx.x;
    if (i < EE) {
        int d = ei[EE + i];
        int pos = atomicAdd(&g_fill[d], 1);
        g_col[pos] = ei[i];
    }
}

// ---------------- both-encoder concat ----------------
__global__ void concat2_kernel(const float4* __restrict__ ueo, const float4* __restrict__ ieo,
                               const float4* __restrict__ uet, const float4* __restrict__ iet) {
    int i = blockIdx.x * blockDim.x + threadIdx.x;
    const int PER = NN * (F / 4);
    const int UQ  = NUSER * (F / 4);
    if (i >= 2 * PER) return;
    int enc = (i >= PER) ? 1 : 0;
    int j = i - enc * PER;
    float4 v;
    if (j < UQ) v = enc ? uet[j] : ueo[j];
    else        v = enc ? iet[j - UQ] : ieo[j - UQ];
    ((float4*)g_x[enc])[j] = v;
}

// ---------------- WMMA gemm (h = x @ W, fp16 in / fp32 acc) + fused dots ----
// smem layout (40KB): [0,8K) W half; [8K,24K) X half (consumed by MMA);
//                     [8K,40K) C float (written after MMA; unions X).
__global__ void __launch_bounds__(256) gemm_dots_kernel(
    const float* __restrict__ Wo, const float* __restrict__ Wt,
    const float* __restrict__ aso, const float* __restrict__ ado,
    const float* __restrict__ ast, const float* __restrict__ adt) {
    int enc = blockIdx.y;
    const float* W   = enc ? Wt  : Wo;
    const float* avs = enc ? ast : aso;
    const float* avd = enc ? adt : ado;

    __shared__ __align__(16) char smem[40960];
    half*  Wh = (half*)smem;
    half*  Xh = (half*)(smem + 8192);
    float* Cs = (float*)(smem + 8192);

    int tid = threadIdx.x;
    int r0  = blockIdx.x * GR;

    // load W (64x64 fp32 -> fp16)
    {
        const float4* W4 = (const float4*)W;
#pragma unroll
        for (int i = 0; i < 4; i++) {
            int idx = tid + i * 256;              // float4 index, 1024 total
            float4 v = W4[idx];
            half2* dst = (half2*)(Wh + idx * 4);
            dst[0] = __floats2half2_rn(v.x, v.y);
            dst[1] = __floats2half2_rn(v.z, v.w);
        }
    }
    // load X tile (GR x 64 fp32 -> fp16), zero-pad rows >= NN
    {
        const float4* X4 = (const float4*)(g_x[enc] + (size_t)r0 * F);
#pragma unroll
        for (int i = 0; i < 8; i++) {
            int idx = tid + i * 256;              // float4 index, 2048 total
            int row = idx >> 4;
            float4 v = make_float4(0.f, 0.f, 0.f, 0.f);
            if (r0 + row < NN) v = X4[idx];
            half2* dst = (half2*)(Xh + idx * 4);
            dst[0] = __floats2half2_rn(v.x, v.y);
            dst[1] = __floats2half2_rn(v.z, v.w);
        }
    }
    __syncthreads();

    int wid = tid >> 5, lane = tid & 31;

    wmma::fragment<wmma::accumulator, 16, 16, 16, float> cfrag[4];
#pragma unroll
    for (int n = 0; n < 4; n++) wmma::fill_fragment(cfrag[n], 0.0f);
#pragma unroll
    for (int k = 0; k < 4; k++) {
        wmma::fragment<wmma::matrix_a, 16, 16, 16, half, wmma::row_major> afrag;
        wmma::load_matrix_sync(afrag, Xh + (wid * 16) * 64 + k * 16, 64);
#pragma unroll
        for (int n = 0; n < 4; n++) {
            wmma::fragment<wmma::matrix_b, 16, 16, 16, half, wmma::row_major> bfrag;
            wmma::load_matrix_sync(bfrag, Wh + (k * 16) * 64 + n * 16, 64);
            wmma::mma_sync(cfrag[n], afrag, bfrag, cfrag[n]);
        }
    }
    __syncthreads();   // everyone done reading Xh before Cs overwrites it
#pragma unroll
    for (int n = 0; n < 4; n++)
        wmma::store_matrix_sync(Cs + (wid * 16) * 64 + n * 16, cfrag[n], 64, wmma::mem_row_major);
    __syncthreads();

    // interleaved fp16 h store
    int c = tid & 63;
    int ioff = ((c >> 1) << 2) + (enc << 1) + (c & 1);
    int rbase = (tid >> 6) * 32;
#pragma unroll
    for (int i = 0; i < 32; i++) {
        int r = rbase + i;
        int gr = r0 + r;
        if (gr < NN) g_hih[(size_t)gr * 128 + ioff] = __float2half(Cs[r * 64 + c]);
    }

    // fused dots (fp32): 8 warps x 16 rows
    float a0 = avs[lane], a1 = avs[32 + lane];
    float d0 = avd[lane], d1 = avd[32 + lane];
#pragma unroll
    for (int rr = 0; rr < 16; rr++) {
        int r = wid * 16 + rr;
        float h0 = Cs[r * 64 + lane];
        float h1 = Cs[r * 64 + 32 + lane];
        float s  = h0 * a0 + h1 * a1;
        float dd = h0 * d0 + h1 * d1;
#pragma unroll
        for (int o = 16; o; o >>= 1) {
            s  += __shfl_xor_sync(0xffffffffu, s,  o);
            dd += __shfl_xor_sync(0xffffffffu, dd, o);
        }
        int gr = r0 + r;
        if (lane == 0 && gr < NN) {
            ((float*)g_as2)[2 * gr + enc] = s;
            ((float*)g_ad2)[2 * gr + enc] = dd;
        }
    }
}

// ---------------- single-pass dual-encoder GAT aggregation (fp16 messages) ----
__global__ void __launch_bounds__(256) agg2_kernel(const float* __restrict__ bo,
                                                   const float* __restrict__ bt) {
    int d = (blockIdx.x * blockDim.x + threadIdx.x) >> 5;
    int lane = threadIdx.x & 31;
    if (d >= NN) return;

    const uint2* hi2 = (const uint2*)g_hih;   // 8 B per lane per node

    int s0 = g_rowptr[d];
    int s1 = g_rowptr[d + 1];
    float2 adv = g_ad2[d];
    float2 asv = g_as2[d];
    float m0 = lrelu(asv.x + adv.x);     // running maxes; self weight starts at 1
    float m1 = lrelu(asv.y + adv.y);

    uint2 hd = hi2[(size_t)d * 32 + lane];
    float2 f0 = __half22float2(*(__half2*)&hd.x);
    float2 f1 = __half22float2(*(__half2*)&hd.y);
    float acc0x = f0.x, acc0y = f0.y;    // self message, weight exp(e_self - m) = 1
    float acc1x = f1.x, acc1y = f1.y;
    float den0 = (lane == 0) ? 1.f : 0.f;
    float den1 = den0;

    for (int base = s0; base < s1; base += 32) {
        int k = base + lane;
        bool valid = k < s1;
        int s = valid ? g_col[k] : 0;
        float e0 = -1e30f, e1 = -1e30f;
        if (valid) {
            float2 a = g_as2[s];
            e0 = lrelu(a.x + adv.x);
            e1 = lrelu(a.y + adv.y);
        }
        // warp-wide chunk maxes
        float c0 = e0, c1 = e1;
#pragma unroll
        for (int o = 16; o; o >>= 1) {
            c0 = fmaxf(c0, __shfl_xor_sync(0xffffffffu, c0, o));
            c1 = fmaxf(c1, __shfl_xor_sync(0xffffffffu, c1, o));
        }
        if (c0 > m0) { float sc = __expf(m0 - c0); acc0x *= sc; acc0y *= sc; den0 *= sc; m0 = c0; }
        if (c1 > m1) { float sc = __expf(m1 - c1); acc1x *= sc; acc1y *= sc; den1 *= sc; m1 = c1; }

        float w0 = valid ? __expf(e0 - m0) : 0.f;
        float w1 = valid ? __expf(e1 - m1) : 0.f;
        den0 += w0;
        den1 += w1;

        int cnt = min(32, s1 - base);
        int padded = (cnt + 3) & ~3;     // padded lanes carry w=0, s=0 -> no-ops
        for (int j = 0; j < padded; j += 4) {
            int sj0 = __shfl_sync(0xffffffffu, s, j + 0);
            int sj1 = __shfl_sync(0xffffffffu, s, j + 1);
            int sj2 = __shfl_sync(0xffffffffu, s, j + 2);
            int sj3 = __shfl_sync(0xffffffffu, s, j + 3);
            uint2 v0 = hi2[(size_t)sj0 * 32 + lane];
            uint2 v1 = hi2[(size_t)sj1 * 32 + lane];
            uint2 v2 = hi2[(size_t)sj2 * 32 + lane];
            uint2 v3 = hi2[(size_t)sj3 * 32 + lane];
            float a0w = __shfl_sync(0xffffffffu, w0, j + 0);
            float b0w = __shfl_sync(0xffffffffu, w1, j + 0);
            float a1w = __shfl_sync(0xffffffffu, w0, j + 1);
            float b1w = __shfl_sync(0xffffffffu, w1, j + 1);
            float a2w = __shfl_sync(0xffffffffu, w0, j + 2);
            float b2w = __shfl_sync(0xffffffffu, w1, j + 2);
            float a3w = __shfl_sync(0xffffffffu, w0, j + 3);
            float b3w = __shfl_sync(0xffffffffu, w1, j + 3);
            float2 p, q;
            p = __half22float2(*(__half2*)&v0.x); q = __half22float2(*(__half2*)&v0.y);
            acc0x = fmaf(a0w, p.x, acc0x);  acc0y = fmaf(a0w, p.y, acc0y);
            acc1x = fmaf(b0w, q.x, acc1x);  acc1y = fmaf(b0w, q.y, acc1y);
            p = __half22float2(*(__half2*)&v1.x); q = __half22float2(*(__half2*)&v1.y);
            acc0x = fmaf(a1w, p.x, acc0x);  acc0y = fmaf(a1w, p.y, acc0y);
            acc1x = fmaf(b1w, q.x, acc1x);  acc1y = fmaf(b1w, q.y, acc1y);
            p = __half22float2(*(__half2*)&v2.x); q = __half22float2(*(__half2*)&v2.y);
            acc0x = fmaf(a2w, p.x, acc0x);  acc0y = fmaf(a2w, p.y, acc0y);
            acc1x = fmaf(b2w, q.x, acc1x);  acc1y = fmaf(b2w, q.y, acc1y);
            p = __half22float2(*(__half2*)&v3.x); q = __half22float2(*(__half2*)&v3.y);
            acc0x = fmaf(a3w, p.x, acc0x);  acc0y = fmaf(a3w, p.y, acc0y);
            acc1x = fmaf(b3w, q.x, acc1x);  acc1y = fmaf(b3w, q.y, acc1y);
        }
    }
#pragma unroll
    for (int o = 16; o; o >>= 1) {
        den0 += __shfl_xor_sync(0xffffffffu, den0, o);
        den1 += __shfl_xor_sync(0xffffffffu, den1, o);
    }
    float inv0 = 1.f / den0;
    float inv1 = 1.f / den1;

    float2 o0, o1;
    o0.x = acc0x * inv0 + bo[2 * lane];
    o0.y = acc0y * inv0 + bo[2 * lane + 1];
    o1.x = acc1x * inv1 + bt[2 * lane];
    o1.y = acc1y * inv1 + bt[2 * lane + 1];
    ((float2*)g_x[0])[(size_t)d * 32 + lane] = o0;
    ((float2*)g_x[1])[(size_t)d * 32 + lane] = o1;
}

// ---------------- predictor + output assembly ----------------
__global__ void __launch_bounds__(256) final_kernel(const float* __restrict__ pW,
                                                    const float* __restrict__ pb,
                                                    const int* __restrict__ user,
                                                    const int* __restrict__ item,
                                                    float* __restrict__ out) {
    __shared__ float Ws[64 * 65];
    __shared__ float rows[4 * 64];
    int tid = threadIdx.x;
    bool isU = blockIdx.x < (Q / 4);
    int qb = (isU ? blockIdx.x : blockIdx.x - (Q / 4)) * 4;

    for (int i = tid; i < 4096; i += 256) Ws[(i >> 6) * 65 + (i & 63)] = pW[i];

    int qr = tid >> 6, c = tid & 63;
    int q = qb + qr;
    int node = isU ? user[q] : (NUSER + item[q]);
    rows[qr * 64 + c] = g_x[0][(size_t)node * F + c];
    __syncthreads();

    float acc = pb[c];
#pragma unroll
    for (int k = 0; k < 64; k++) acc = fmaf(rows[qr * 64 + k], Ws[c * 65 + k], acc);

    size_t base = isU ? 0 : (size_t)2 * Q * F;
    out[base + (size_t)q * F + c] = acc;                                  // predicted
    out[base + (size_t)Q * F + (size_t)q * F + c] = g_x[1][(size_t)node * F + c];  // target
}

// ---------------- host ----------------
extern "C" void kernel_launch(void* const* d_in, const int* in_sizes, int n_in,
                              void* d_out, int out_size) {
    const float *uembo, *iembo, *Wo, *aso, *ado, *bo;
    const float *uembt, *iembt, *Wt, *ast, *adt, *bt;
    const float *pW, *pb;
    const int *user, *item, *ei;

    if (in_sizes[0] == Q) {  // setup_inputs dict order
        user  = (const int*)d_in[0];
        item  = (const int*)d_in[1];
        ei    = (const int*)d_in[2];
        uembo = (const float*)d_in[3];  iembo = (const float*)d_in[4];
        Wo    = (const float*)d_in[5];
        aso   = (const float*)d_in[6];  ado   = (const float*)d_in[7];  bo = (const float*)d_in[8];
        uembt = (const float*)d_in[9];  iembt = (const float*)d_in[10];
        Wt    = (const float*)d_in[11];
        ast   = (const float*)d_in[12]; adt   = (const float*)d_in[13]; bt = (const float*)d_in[14];
        pW    = (const float*)d_in[15]; pb    = (const float*)d_in[16];
    } else {                 // reference signature order
        uembo = (const float*)d_in[0];  iembo = (const float*)d_in[1];
        Wo    = (const float*)d_in[2];
        aso   = (const float*)d_in[3];  ado   = (const float*)d_in[4];  bo = (const float*)d_in[5];
        uembt = (const float*)d_in[6];  iembt = (const float*)d_in[7];
        Wt    = (const float*)d_in[8];
        ast   = (const float*)d_in[9];  adt   = (const float*)d_in[10]; bt = (const float*)d_in[11];
        pW    = (const float*)d_in[12]; pb    = (const float*)d_in[13];
        user  = (const int*)d_in[14];
        item  = (const int*)d_in[15];
        ei    = (const int*)d_in[16];
    }
    float* out = (float*)d_out;

    zero_counts_kernel<<<(NN + 255) / 256, 256>>>();
    hist_kernel<<<EE / 256, 256>>>(ei);
    scan_kernel<<<1, 1024>>>();
    scatter_kernel<<<EE / 256, 256>>>(ei);

    concat2_kernel<<<(2 * NN * (F / 4) + 255) / 256, 256>>>(
        (const float4*)uembo, (const float4*)iembo,
        (const float4*)uembt, (const float4*)iembt);

    const int GEMM_BLOCKS = (NN + GR - 1) / GR;  // 1172
    const int WARP_BLOCKS = NN / 8;              // 18750

    for (int l = 0; l < 3; l++) {
        dim3 gg(GEMM_BLOCKS, 2);
        gemm_dots_kernel<<<gg, 256>>>(Wo + (size_t)l * F * F, Wt + (size_t)l * F * F,
                                      aso + l * F, ado + l * F, ast + l * F, adt + l * F);
        agg2_kernel<<<WARP_BLOCKS, 256>>>(bo + l * F, bt + l * F);
    }

    final_kernel<<<2 * (Q / 4), 256>>>(pW, pb, user, item, out);
}

// round 9
// speedup vs baseline: 1.8157x; 1.0455x over previous
#include <cuda_runtime.h>
#include <cuda_fp16.h>
#include <mma.h>
using namespace nvcuda;

#define NUSER 100000
#define NITEM 50000
#define NN    150000
#define EE    2400000
#define F     64
#define Q     4096
#define GR    128               // rows per gemm block
#define NEG_SLOPE 0.2f

// ---------------- device scratch (no allocs allowed) ----------------
__device__ __align__(16) float  g_x[2][NN * F];    // [0]=online, [1]=target (fp32)
__device__ __align__(16) __half g_hih[NN * 2 * F]; // fp16 interleaved h:
                                                   // idx = r*128 + (c>>1)*4 + enc*2 + (c&1)
__device__ __align__(8)  float2 g_as2[NN];         // (as_online, as_target) fp32
__device__ __align__(8)  float2 g_ad2[NN];         // (ad_online, ad_target) fp32
__device__ int g_rowptr[NN + 1];
__device__ int g_fill[NN];
__device__ int g_col[EE];

__device__ __forceinline__ float lrelu(float v) { return fmaxf(v, NEG_SLOPE * v); }

// ---------------- CSR build ----------------
__global__ void zero_counts_kernel() {
    int i = blockIdx.x * blockDim.x + threadIdx.x;
    if (i < NN) g_fill[i] = 0;
}

__global__ void hist_kernel(const int* __restrict__ ei) {
    int i = blockIdx.x * blockDim.x + threadIdx.x;
    if (i < EE) atomicAdd(&g_fill[__ldcs(ei + EE + i)], 1);
}

__global__ void scan_kernel() {
    __shared__ int sb[1024];
    int t = threadIdx.x;
    const int CH = 147;
    int start = t * CH;
    int end = min(start + CH, NN);
    int s = 0;
    for (int i = start; i < end; i++) s += g_fill[i];
    sb[t] = s;
    __syncthreads();
    for (int o = 1; o < 1024; o <<= 1) {
        int v = 0;
        if (t >= o) v = sb[t - o];
        __syncthreads();
        if (t >= o) sb[t] += v;
        __syncthreads();
    }
    int run = (t == 0) ? 0 : sb[t - 1];
    for (int i = start; i < end; i++) {
        int cnt = g_fill[i];
        g_rowptr[i] = run;
        g_fill[i]   = run;
        run += cnt;
    }
    if (t == 1023) g_rowptr[NN] = sb[1023];
}

__global__ void scatter_kernel(const int* __restrict__ ei) {
    int i = blockIdx.x * blockDim.x + threadIdx.x;
    if (i < EE) {
        int d = __ldcs(ei + EE + i);
        int pos = atomicAdd(&g_fill[d], 1);
        g_col[pos] = __ldcs(ei + i);
    }
}

// ---------------- WMMA gemm (h = x @ W, fp16 in / fp32 acc) + fused dots ----
// Reads X from (Xu | Xi) split at row NUSER (layer 1: raw embeddings;
// layers 2+: g_x[enc] halves) with streaming loads.
// smem layout (40KB): [0,8K) W half; [8K,24K) X half; [8K,40K) C float (unions X).
__global__ void __launch_bounds__(256) gemm_dots_kernel(
    const float* __restrict__ Xu0, const float* __restrict__ Xi0,
    const float* __restrict__ Xu1, const float* __restrict__ Xi1,
    const float* __restrict__ Wo, const float* __restrict__ Wt,
    const float* __restrict__ aso, const float* __restrict__ ado,
    const float* __restrict__ ast, const float* __restrict__ adt) {
    int enc = blockIdx.y;
    const float* W   = enc ? Wt  : Wo;
    const float* avs = enc ? ast : aso;
    const float* avd = enc ? adt : ado;
    const float* Xu  = enc ? Xu1 : Xu0;
    const float* Xi  = enc ? Xi1 : Xi0;

    __shared__ __align__(16) char smem[40960];
    half*  Wh = (half*)smem;
    half*  Xh = (half*)(smem + 8192);
    float* Cs = (float*)(smem + 8192);

    int tid = threadIdx.x;
    int r0  = blockIdx.x * GR;

    // load W (64x64 fp32 -> fp16)
    {
        const float4* W4 = (const float4*)W;
#pragma unroll
        for (int i = 0; i < 4; i++) {
            int idx = tid + i * 256;              // float4 index, 1024 total
            float4 v = W4[idx];
            half2* dst = (half2*)(Wh + idx * 4);
            dst[0] = __floats2half2_rn(v.x, v.y);
            dst[1] = __floats2half2_rn(v.z, v.w);
        }
    }
    // load X tile (GR x 64 fp32 -> fp16), user/item split, streaming
    {
#pragma unroll
        for (int i = 0; i < 8; i++) {
            int idx = tid + i * 256;              // float4 index, 2048 total
            int row = idx >> 4;
            int q   = idx & 15;
            int gr  = r0 + row;
            float4 v = make_float4(0.f, 0.f, 0.f, 0.f);
            if (gr < NUSER)      v = __ldcs((const float4*)(Xu + (size_t)gr * F) + q);
            else if (gr < NN)    v = __ldcs((const float4*)(Xi + (size_t)(gr - NUSER) * F) + q);
            half2* dst = (half2*)(Xh + idx * 4);
            dst[0] = __floats2half2_rn(v.x, v.y);
            dst[1] = __floats2half2_rn(v.z, v.w);
        }
    }
    __syncthreads();

    int wid = tid >> 5, lane = tid & 31;

    wmma::fragment<wmma::accumulator, 16, 16, 16, float> cfrag[4];
#pragma unroll
    for (int n = 0; n < 4; n++) wmma::fill_fragment(cfrag[n], 0.0f);
#pragma unroll
    for (int k = 0; k < 4; k++) {
        wmma::fragment<wmma::matrix_a, 16, 16, 16, half, wmma::row_major> afrag;
        wmma::load_matrix_sync(afrag, Xh + (wid * 16) * 64 + k * 16, 64);
#pragma unroll
        for (int n = 0; n < 4; n++) {
            wmma::fragment<wmma::matrix_b, 16, 16, 16, half, wmma::row_major> bfrag;
            wmma::load_matrix_sync(bfrag, Wh + (k * 16) * 64 + n * 16, 64);
            wmma::mma_sync(cfrag[n], afrag, bfrag, cfrag[n]);
        }
    }
    __syncthreads();   // everyone done reading Xh before Cs overwrites it
#pragma unroll
    for (int n = 0; n < 4; n++)
        wmma::store_matrix_sync(Cs + (wid * 16) * 64 + n * 16, cfrag[n], 64, wmma::mem_row_major);
    __syncthreads();

    // interleaved fp16 h store (keep cached: agg re-reads it ~17x)
    int c = tid & 63;
    int ioff = ((c >> 1) << 2) + (enc << 1) + (c & 1);
    int rbase = (tid >> 6) * 32;
#pragma unroll
    for (int i = 0; i < 32; i++) {
        int r = rbase + i;
        int gr = r0 + r;
        if (gr < NN) g_hih[(size_t)gr * 128 + ioff] = __float2half(Cs[r * 64 + c]);
    }

    // fused dots (fp32): 8 warps x 16 rows
    float a0 = avs[lane], a1 = avs[32 + lane];
    float d0 = avd[lane], d1 = avd[32 + lane];
#pragma unroll
    for (int rr = 0; rr < 16; rr++) {
        int r = wid * 16 + rr;
        float h0 = Cs[r * 64 + lane];
        float h1 = Cs[r * 64 + 32 + lane];
        float s  = h0 * a0 + h1 * a1;
        float dd = h0 * d0 + h1 * d1;
#pragma unroll
        for (int o = 16; o; o >>= 1) {
            s  += __shfl_xor_sync(0xffffffffu, s,  o);
            dd += __shfl_xor_sync(0xffffffffu, dd, o);
        }
        int gr = r0 + r;
        if (lane == 0 && gr < NN) {
            ((float*)g_as2)[2 * gr + enc] = s;
            ((float*)g_ad2)[2 * gr + enc] = dd;
        }
    }
}

// ---------------- single-pass dual-encoder GAT aggregation (fp16 messages) ----
__global__ void __launch_bounds__(256) agg2_kernel(const float* __restrict__ bo,
                                                   const float* __restrict__ bt) {
    int d = (blockIdx.x * blockDim.x + threadIdx.x) >> 5;
    int lane = threadIdx.x & 31;
    if (d >= NN) return;

    const uint2* hi2 = (const uint2*)g_hih;   // 8 B per lane per node

    int s0 = g_rowptr[d];
    int s1 = g_rowptr[d + 1];
    float2 adv = g_ad2[d];
    float2 asv = g_as2[d];
    float m0 = lrelu(asv.x + adv.x);     // running maxes; self weight starts at 1
    float m1 = lrelu(asv.y + adv.y);

    uint2 hd = hi2[(size_t)d * 32 + lane];
    float2 f0 = __half22float2(*(__half2*)&hd.x);
    float2 f1 = __half22float2(*(__half2*)&hd.y);
    float acc0x = f0.x, acc0y = f0.y;    // self message, weight exp(e_self - m) = 1
    float acc1x = f1.x, acc1y = f1.y;
    float den0 = (lane == 0) ? 1.f : 0.f;
    float den1 = den0;

    for (int base = s0; base < s1; base += 32) {
        int k = base + lane;
        bool valid = k < s1;
        int s = valid ? __ldcs(&g_col[k]) : 0;
        float e0 = -1e30f, e1 = -1e30f;
        if (valid) {
            float2 a = g_as2[s];
            e0 = lrelu(a.x + adv.x);
            e1 = lrelu(a.y + adv.y);
        }
        // warp-wide chunk maxes
        float c0 = e0, c1 = e1;
#pragma unroll
        for (int o = 16; o; o >>= 1) {
            c0 = fmaxf(c0, __shfl_xor_sync(0xffffffffu, c0, o));
            c1 = fmaxf(c1, __shfl_xor_sync(0xffffffffu, c1, o));
        }
        if (c0 > m0) { float sc = __expf(m0 - c0); acc0x *= sc; acc0y *= sc; den0 *= sc; m0 = c0; }
        if (c1 > m1) { float sc = __expf(m1 - c1); acc1x *= sc; acc1y *= sc; den1 *= sc; m1 = c1; }

        float w0 = valid ? __expf(e0 - m0) : 0.f;
        float w1 = valid ? __expf(e1 - m1) : 0.f;
        den0 += w0;
        den1 += w1;

        int cnt = min(32, s1 - base);
        int padded = (cnt + 3) & ~3;     // padded lanes carry w=0, s=0 -> no-ops
        for (int j = 0; j < padded; j += 4) {
            int sj0 = __shfl_sync(0xffffffffu, s, j + 0);
            int sj1 = __shfl_sync(0xffffffffu, s, j + 1);
            int sj2 = __shfl_sync(0xffffffffu, s, j + 2);
            int sj3 = __shfl_sync(0xffffffffu, s, j + 3);
            uint2 v0 = hi2[(size_t)sj0 * 32 + lane];
            uint2 v1 = hi2[(size_t)sj1 * 32 + lane];
            uint2 v2 = hi2[(size_t)sj2 * 32 + lane];
            uint2 v3 = hi2[(size_t)sj3 * 32 + lane];
            float a0w = __shfl_sync(0xffffffffu, w0, j + 0);
            float b0w = __shfl_sync(0xffffffffu, w1, j + 0);
            float a1w = __shfl_sync(0xffffffffu, w0, j + 1);
            float b1w = __shfl_sync(0xffffffffu, w1, j + 1);
            float a2w = __shfl_sync(0xffffffffu, w0, j + 2);
            float b2w = __shfl_sync(0xffffffffu, w1, j + 2);
            float a3w = __shfl_sync(0xffffffffu, w0, j + 3);
            float b3w = __shfl_sync(0xffffffffu, w1, j + 3);
            float2 p, q;
            p = __half22float2(*(__half2*)&v0.x); q = __half22float2(*(__half2*)&v0.y);
            acc0x = fmaf(a0w, p.x, acc0x);  acc0y = fmaf(a0w, p.y, acc0y);
            acc1x = fmaf(b0w, q.x, acc1x);  acc1y = fmaf(b0w, q.y, acc1y);
            p = __half22float2(*(__half2*)&v1.x); q = __half22float2(*(__half2*)&v1.y);
            acc0x = fmaf(a1w, p.x, acc0x);  acc0y = fmaf(a1w, p.y, acc0y);
            acc1x = fmaf(b1w, q.x, acc1x);  acc1y = fmaf(b1w, q.y, acc1y);
            p = __half22float2(*(__half2*)&v2.x); q = __half22float2(*(__half2*)&v2.y);
            acc0x = fmaf(a2w, p.x, acc0x);  acc0y = fmaf(a2w, p.y, acc0y);
            acc1x = fmaf(b2w, q.x, acc1x);  acc1y = fmaf(b2w, q.y, acc1y);
            p = __half22float2(*(__half2*)&v3.x); q = __half22float2(*(__half2*)&v3.y);
            acc0x = fmaf(a3w, p.x, acc0x);  acc0y = fmaf(a3w, p.y, acc0y);
            acc1x = fmaf(b3w, q.x, acc1x);  acc1y = fmaf(b3w, q.y, acc1y);
        }
    }
#pragma unroll
    for (int o = 16; o; o >>= 1) {
        den0 += __shfl_xor_sync(0xffffffffu, den0, o);
        den1 += __shfl_xor_sync(0xffffffffu, den1, o);
    }
    float inv0 = 1.f / den0;
    float inv1 = 1.f / den1;

    float2 o0, o1;
    o0.x = acc0x * inv0 + bo[2 * lane];
    o0.y = acc0y * inv0 + bo[2 * lane + 1];
    o1.x = acc1x * inv1 + bt[2 * lane];
    o1.y = acc1y * inv1 + bt[2 * lane + 1];
    // evict-first stores: keep g_hih resident in L2 while streaming x out
    __stcs(&((float2*)g_x[0])[(size_t)d * 32 + lane], o0);
    __stcs(&((float2*)g_x[1])[(size_t)d * 32 + lane], o1);
}

// ---------------- predictor + output assembly ----------------
__global__ void __launch_bounds__(256) final_kernel(const float* __restrict__ pW,
                                                    const float* __restrict__ pb,
                                                    const int* __restrict__ user,
                                                    const int* __restrict__ item,
                                                    float* __restrict__ out) {
    __shared__ float Ws[64 * 65];
    __shared__ float rows[4 * 64];
    int tid = threadIdx.x;
    bool isU = blockIdx.x < (Q / 4);
    int qb = (isU ? blockIdx.x : blockIdx.x - (Q / 4)) * 4;

    for (int i = tid; i < 4096; i += 256) Ws[(i >> 6) * 65 + (i & 63)] = pW[i];

    int qr = tid >> 6, c = tid & 63;
    int q = qb + qr;
    int node = isU ? user[q] : (NUSER + item[q]);
    rows[qr * 64 + c] = g_x[0][(size_t)node * F + c];
    __syncthreads();

    float acc = pb[c];
#pragma unroll
    for (int k = 0; k < 64; k++) acc = fmaf(rows[qr * 64 + k], Ws[c * 65 + k], acc);

    size_t base = isU ? 0 : (size_t)2 * Q * F;
    out[base + (size_t)q * F + c] = acc;                                  // predicted
    out[base + (size_t)Q * F + (size_t)q * F + c] = g_x[1][(size_t)node * F + c];  // target
}

// ---------------- host ----------------
extern "C" void kernel_launch(void* const* d_in, const int* in_sizes, int n_in,
                              void* d_out, int out_size) {
    const float *uembo, *iembo, *Wo, *aso, *ado, *bo;
    const float *uembt, *iembt, *Wt, *ast, *adt, *bt;
    const float *pW, *pb;
    const int *user, *item, *ei;

    if (in_sizes[0] == Q) {  // setup_inputs dict order
        user  = (const int*)d_in[0];
        item  = (const int*)d_in[1];
        ei    = (const int*)d_in[2];
        uembo = (const float*)d_in[3];  iembo = (const float*)d_in[4];
        Wo    = (const float*)d_in[5];
        aso   = (const float*)d_in[6];  ado   = (const float*)d_in[7];  bo = (const float*)d_in[8];
        uembt = (const float*)d_in[9];  iembt = (const float*)d_in[10];
        Wt    = (const float*)d_in[11];
        ast   = (const float*)d_in[12]; adt   = (const float*)d_in[13]; bt = (const float*)d_in[14];
        pW    = (const float*)d_in[15]; pb    = (const float*)d_in[16];
    } else {                 // reference signature order
        uembo = (const float*)d_in[0];  iembo = (const float*)d_in[1];
        Wo    = (const float*)d_in[2];
        aso   = (const float*)d_in[3];  ado   = (const float*)d_in[4];  bo = (const float*)d_in[5];
        uembt = (const float*)d_in[6];  iembt = (const float*)d_in[7];
        Wt    = (const float*)d_in[8];
        ast   = (const float*)d_in[9];  adt   = (const float*)d_in[10]; bt = (const float*)d_in[11];
        pW    = (const float*)d_in[12]; pb    = (const float*)d_in[13];
        user  = (const int*)d_in[14];
        item  = (const int*)d_in[15];
        ei    = (const int*)d_in[16];
    }
    float* out = (float*)d_out;

    zero_counts_kernel<<<(NN + 255) / 256, 256>>>();
    hist_kernel<<<EE / 256, 256>>>(ei);
    scan_kernel<<<1, 1024>>>();
    scatter_kernel<<<EE / 256, 256>>>(ei);

    const int GEMM_BLOCKS = (NN + GR - 1) / GR;  // 1172
    const int WARP_BLOCKS = NN / 8;              // 18750

    // x base pointers per encoder; l==0 reads embeddings directly
    const float* gx0 = nullptr;   // filled per layer below
    for (int l = 0; l < 3; l++) {
        dim3 gg(GEMM_BLOCKS, 2);
        const float *Xu0, *Xi0, *Xu1, *Xi1;
        if (l == 0) {
            Xu0 = uembo; Xi0 = iembo; Xu1 = uembt; Xi1 = iembt;
        } else {
            // g_x device symbols: take addresses via a device-symbol trick is
            // not needed — gemm can read g_x directly, but we pass pointers
            // obtained from the symbol address at first use.
            // cudaGetSymbolAddress is not graph-capture-hostile (host-side, no alloc).
            static float* gx_base = nullptr;
            if (!gx_base) cudaGetSymbolAddress((void**)&gx_base, g_x);
            Xu0 = gx_base;
            Xi0 = gx_base + (size_t)NUSER * F;
            Xu1 = gx_base + (size_t)NN * F;
            Xi1 = gx_base + (size_t)NN * F + (size_t)NUSER * F;
        }
        gemm_dots_kernel<<<gg, 256>>>(Xu0, Xi0, Xu1, Xi1,
                                      Wo + (size_t)l * F * F, Wt + (size_t)l * F * F,
                                      aso + l * F, ado + l * F, ast + l * F, adt + l * F);
        agg2_kernel<<<WARP_BLOCKS, 256>>>(bo + l * F, bt + l * F);
    }
    (void)gx0;

    final_kernel<<<2 * (Q / 4), 256>>>(pW, pb, user, item, out);
}